// round 5
// baseline (speedup 1.0000x reference)
#include <cuda_runtime.h>
#include <math.h>
#include <stdint.h>

// Problem constants
#define BATCH 128
#define NOBJ  36
#define NNODE (BATCH*NOBJ)   // 4608
#define QD    2400
#define QDP   2432

__device__ __forceinline__ uint32_t smem_u32(const void* p) {
    uint32_t a;
    asm("{ .reg .u64 t; cvta.to.shared.u64 t, %1; cvt.u32.u64 %0, t; }" : "=r"(a) : "l"(p));
    return a;
}
__device__ __forceinline__ void cpa16(uint32_t s, const void* g) {
    asm volatile("cp.async.cg.shared.global [%0], [%1], 16;" :: "r"(s), "l"(g));
}
#define CP_COMMIT() asm volatile("cp.async.commit_group;" ::: "memory")
#define CP_WAIT1()  asm volatile("cp.async.wait_group 1;" ::: "memory")
#define CP_WAIT0()  asm volatile("cp.async.wait_group 0;" ::: "memory")

__device__ __forceinline__ uint32_t lds32(uint32_t addr) {
    uint32_t v;
    asm("ld.shared.b32 %0, [%1];" : "=r"(v) : "r"(addr));
    return v;
}
__device__ __forceinline__ void mma_s8(int32_t* c, const uint32_t* a, uint32_t b0, uint32_t b1) {
    asm volatile(
        "mma.sync.aligned.m16n8k32.row.col.s32.s8.s8.s32 "
        "{%0,%1,%2,%3}, {%4,%5,%6,%7}, {%8,%9}, {%0,%1,%2,%3};"
        : "+r"(c[0]), "+r"(c[1]), "+r"(c[2]), "+r"(c[3])
        : "r"(a[0]), "r"(a[1]), "r"(a[2]), "r"(a[3]), "r"(b0), "r"(b1));
}

// ==================== scratch (no allocations allowed) ====================
// int8 slices (hi = x128 slice, lo = unit slice), per-row scales
__device__ __align__(128) int8_t g_qe1[128 * QDP];
__device__ __align__(128) int8_t g_qe0[128 * QDP];
__device__ __align__(128) int8_t g_ob1[NNODE * 2048];
__device__ __align__(128) int8_t g_ob0[NNODE * 2048];
__device__ __align__(128) int8_t g_Wq1[2048 * QDP];
__device__ __align__(128) int8_t g_Wq0[2048 * QDP];
__device__ __align__(128) int8_t g_Wv1[2048 * 2048];
__device__ __align__(128) int8_t g_Wv0[2048 * 2048];
__device__ __align__(128) int8_t g_W11[1024 * 2048];
__device__ __align__(128) int8_t g_W10[1024 * 2048];
__device__ __align__(128) int8_t g_W21[1024 * 1024];
__device__ __align__(128) int8_t g_W20[1024 * 1024];
__device__ __align__(128) int8_t g_W31[2560 * 1024];
__device__ __align__(128) int8_t g_W30[2560 * 1024];
__device__ __align__(128) int8_t g_x1 [NNODE * 2048];
__device__ __align__(128) int8_t g_x0 [NNODE * 2048];
__device__ __align__(128) int8_t g_g11[NNODE * 1024];
__device__ __align__(128) int8_t g_g10[NNODE * 1024];
__device__ __align__(128) int8_t g_g21[NNODE * 1024];
__device__ __align__(128) int8_t g_g20[NNODE * 1024];

__device__ float g_sQe[128];
__device__ float g_sOb[NNODE];
__device__ float g_sWq[2048];
__device__ float g_sWv[2048];
__device__ float g_sW1[1024];
__device__ float g_sW2[1024];
__device__ float g_sW3[2560];
__device__ float g_sX [NNODE];
__device__ float g_sG1[NNODE];
__device__ float g_sG2[NNODE];

__device__ float g_WTf  [2048 * QDP];        // transpose scratch (max: Wq 2048x2432)
__device__ float g_q    [128 * 2048];
__device__ float g_qpart[4 * 128 * 2048];
__device__ float g_xf   [NNODE * 2048];
__device__ float g_h    [NNODE * 2560];
__device__ float g_g1   [NNODE * 1024];
__device__ float g_g2   [NNODE * 1024];
__device__ float g_als  [NNODE * 5];
__device__ float g_ald  [NNODE * 5];

// ==================== prep kernels ====================
// transpose: W [K,N] fp32 -> WT [N,Kp] fp32 (zero pad K..Kp)
__global__ __launch_bounds__(256) void tr_k(const float* __restrict__ W, float* __restrict__ WT,
                                            int K, int N, int Kp)
{
    __shared__ float t[32][33];
    int n0 = blockIdx.x * 32, k0 = blockIdx.y * 32;
    int tx = threadIdx.x & 31, ty = threadIdx.x >> 5;
    #pragma unroll
    for (int i = 0; i < 4; i++) {
        int k = k0 + ty + i * 8;
        t[ty + i * 8][tx] = (k < K) ? W[(size_t)k * N + n0 + tx] : 0.f;
    }
    __syncthreads();
    #pragma unroll
    for (int i = 0; i < 4; i++) {
        int n = n0 + ty + i * 8;
        WT[(size_t)n * Kp + k0 + tx] = t[tx][ty + i * 8];
    }
}

// per-row int8 2-slice quantization: in [R,C] fp32 -> hi/lo [R,Cp] s8, scale[R]
// a ~= scale * (128*hi + lo), |128*hi+lo| <= 16256
__global__ __launch_bounds__(256) void slice_k(const float* __restrict__ in, int C, int Cp,
                                               int8_t* __restrict__ hi, int8_t* __restrict__ lo,
                                               float* __restrict__ scale)
{
    __shared__ float red[8];
    const int r = blockIdx.x, tid = threadIdx.x;
    const float* row = in + (size_t)r * C;
    float m = 0.f;
    for (int c = tid; c < C; c += 256) m = fmaxf(m, fabsf(row[c]));
    #pragma unroll
    for (int o = 16; o > 0; o >>= 1) m = fmaxf(m, __shfl_xor_sync(0xffffffffu, m, o));
    if ((tid & 31) == 0) red[tid >> 5] = m;
    __syncthreads();
    if (tid == 0) {
        float mm = red[0];
        #pragma unroll
        for (int i = 1; i < 8; i++) mm = fmaxf(mm, red[i]);
        red[0] = mm;
        scale[r] = (mm > 0.f) ? mm / 16256.f : 1.f;
    }
    __syncthreads();
    float rowmax = red[0];
    float inv = (rowmax > 0.f) ? 16256.f / rowmax : 0.f;
    for (int c = tid; c < Cp; c += 256) {
        float a = (c < C) ? row[c] : 0.f;
        float t = rintf(a * inv);                 // |t| <= 16256
        float t1 = rintf(t * 0.0078125f);         // /128
        t1 = fminf(fmaxf(t1, -127.f), 127.f);
        float t0 = t - 128.f * t1;                // in [-64, 64]
        hi[(size_t)r * Cp + c] = (int8_t)t1;
        lo[(size_t)r * Cp + c] = (int8_t)t0;
    }
}

__global__ void combq_k(const float* __restrict__ parts, const float* __restrict__ bq, float* __restrict__ q)
{
    int idx = blockIdx.x * blockDim.x + threadIdx.x;
    if (idx >= 128 * 2048) return;
    const size_t S = (size_t)128 * 2048;
    int c = idx & 2047;
    q[idx] = bq[c] + parts[idx] + parts[idx + S] + parts[idx + 2*S] + parts[idx + 3*S];
}

// ==================== int8x3 GEMM ====================
// C[M,N] = sA[m]*sB[n]*(16384*A1B1 + 128*(A1B0+A0B1)) over K
// A slices [M,Kp] s8 row-major; B slices [N,Kp] s8 row-major (B^T layout)
// CTA tile 128x128, KC=128 k-elements (=128 bytes) per chunk, double buffered
// mode 0: Cf[splitStride*z + row*N + col] = v
// mode 2: Cf = (v + bias[col]) * qmul[(row/36)*N + col]
#define KC 128
#define ROWSTR 144u
#define SLC (128u * ROWSTR)     // 18432 bytes per slice tile
#define BUFSZ (4u * SLC)        // 73728
#define GI_SMEM (2 * BUFSZ + 1024)

__global__ __launch_bounds__(256, 1) void gemm_i8(
    const int8_t* __restrict__ A1, const int8_t* __restrict__ A0, const float* __restrict__ sA,
    const int8_t* __restrict__ B1, const int8_t* __restrict__ B0, const float* __restrict__ sB,
    int N, int Kp, int kcTotal, int kcPerSplit,
    const float* __restrict__ bias, const float* __restrict__ qmul,
    float* __restrict__ Cf, int mode, size_t splitStride)
{
    extern __shared__ char dsm[];
    uint32_t sb = smem_u32(dsm);
    sb = (sb + 1023u) & ~1023u;

    const int tid = threadIdx.x;
    const int wid = tid >> 5;
    const int L   = tid & 31;
    const int m0 = blockIdx.y * 128;
    const int n0 = blockIdx.x * 128;
    const int kc0 = blockIdx.z * kcPerSplit;
    int kc1 = kc0 + kcPerSplit; if (kc1 > kcTotal) kc1 = kcTotal;
    const int ncl = kc1 - kc0;

    const int wm = (wid & 3) * 32;     // 4 warp-rows
    const int wn = (wid >> 2) * 64;    // 2 warp-cols

    int32_t acc1[2][8][4], acc2[2][8][4];
    #pragma unroll
    for (int i = 0; i < 2; i++)
        #pragma unroll
        for (int j = 0; j < 8; j++)
            #pragma unroll
            for (int k = 0; k < 4; k++) { acc1[i][j][k] = 0; acc2[i][j][k] = 0; }

    const int lq = L >> 2;            // 0..7
    const int lr = (L & 3) * 4;       // byte offset within 16B group

    auto load_chunk = [&](int c, int s) {
        const int k0 = c * KC;
        uint32_t base = sb + (uint32_t)s * BUFSZ;
        #pragma unroll
        for (int i = 0; i < 4; i++) {
            int u = tid + i * 256;            // 0..1023
            int r = u >> 3, uc = u & 7;
            uint32_t so = (uint32_t)(r * ROWSTR + uc * 16);
            size_t goA = (size_t)(m0 + r) * Kp + k0 + uc * 16;
            size_t goB = (size_t)(n0 + r) * Kp + k0 + uc * 16;
            cpa16(base + so,            A1 + goA);
            cpa16(base + SLC + so,      A0 + goA);
            cpa16(base + 2u*SLC + so,   B1 + goB);
            cpa16(base + 3u*SLC + so,   B0 + goB);
        }
    };

    load_chunk(kc0, 0); CP_COMMIT();

    for (int cc = 0; cc < ncl; cc++) {
        if (cc + 1 < ncl) {
            load_chunk(kc0 + cc + 1, (cc + 1) & 1);
            CP_COMMIT();
            CP_WAIT1();
        } else {
            CP_WAIT0();
        }
        __syncthreads();

        uint32_t base = sb + (uint32_t)(cc & 1) * BUFSZ;
        #pragma unroll
        for (int ks = 0; ks < 4; ks++) {
            const uint32_t kb = (uint32_t)(ks * 32);
            // A fragments: 2 m-frags x 2 slices x 4 regs
            uint32_t a1f[2][4], a0f[2][4];
            #pragma unroll
            for (int mf = 0; mf < 2; mf++) {
                uint32_t ab = base + (uint32_t)((wm + mf * 16 + lq) * ROWSTR) + kb + lr;
                a1f[mf][0] = lds32(ab);
                a1f[mf][1] = lds32(ab + 8u * ROWSTR);
                a1f[mf][2] = lds32(ab + 16u);
                a1f[mf][3] = lds32(ab + 8u * ROWSTR + 16u);
                uint32_t ab0 = ab + SLC;
                a0f[mf][0] = lds32(ab0);
                a0f[mf][1] = lds32(ab0 + 8u * ROWSTR);
                a0f[mf][2] = lds32(ab0 + 16u);
                a0f[mf][3] = lds32(ab0 + 8u * ROWSTR + 16u);
            }
            #pragma unroll
            for (int half = 0; half < 2; half++) {
                // B fragments: 4 n-frags x 2 slices x 2 regs
                uint32_t b1f[4][2], b0f[4][2];
                #pragma unroll
                for (int nfl = 0; nfl < 4; nfl++) {
                    int n = wn + (half * 4 + nfl) * 8 + lq;
                    uint32_t bb = base + 2u*SLC + (uint32_t)(n * ROWSTR) + kb + lr;
                    b1f[nfl][0] = lds32(bb);
                    b1f[nfl][1] = lds32(bb + 16u);
                    b0f[nfl][0] = lds32(bb + SLC);
                    b0f[nfl][1] = lds32(bb + SLC + 16u);
                }
                // grouped by term to keep RAW chains far apart
                #pragma unroll
                for (int nfl = 0; nfl < 4; nfl++)
                    #pragma unroll
                    for (int mf = 0; mf < 2; mf++)
                        mma_s8(acc1[mf][half*4+nfl], a1f[mf], b1f[nfl][0], b1f[nfl][1]);
                #pragma unroll
                for (int nfl = 0; nfl < 4; nfl++)
                    #pragma unroll
                    for (int mf = 0; mf < 2; mf++)
                        mma_s8(acc2[mf][half*4+nfl], a1f[mf], b0f[nfl][0], b0f[nfl][1]);
                #pragma unroll
                for (int nfl = 0; nfl < 4; nfl++)
                    #pragma unroll
                    for (int mf = 0; mf < 2; mf++)
                        mma_s8(acc2[mf][half*4+nfl], a0f[mf], b1f[nfl][0], b1f[nfl][1]);
            }
        }
        __syncthreads();
    }

    // epilogue
    const int rEp = (L >> 2);
    const int cEp = (L & 3) * 2;
    #pragma unroll
    for (int mf = 0; mf < 2; mf++) {
        #pragma unroll
        for (int half = 0; half < 2; half++) {
            int row = m0 + wm + mf * 16 + rEp + half * 8;
            float sa = sA[row];
            float* dst = Cf + ((mode == 0) ? splitStride * blockIdx.z : 0) + (size_t)row * N;
            const float* qrow = (mode == 2) ? (qmul + (size_t)(row / NOBJ) * N) : nullptr;
            #pragma unroll
            for (int nf = 0; nf < 8; nf++) {
                int col = n0 + wn + nf * 8 + cEp;
                int j0 = half * 2;
                float v0 = sa * sB[col]   * fmaf(16384.f, (float)acc1[mf][nf][j0],   128.f * (float)acc2[mf][nf][j0]);
                float v1 = sa * sB[col+1] * fmaf(16384.f, (float)acc1[mf][nf][j0+1], 128.f * (float)acc2[mf][nf][j0+1]);
                if (mode == 2) {
                    v0 = (v0 + bias[col])   * qrow[col];
                    v1 = (v1 + bias[col+1]) * qrow[col+1];
                }
                float2 v; v.x = v0; v.y = v1;
                *(float2*)(dst + col) = v;
            }
        }
    }
}

// ==================== attention logits ====================
__global__ void al_k(const float* __restrict__ h,
                     const float* __restrict__ a_s, const float* __restrict__ a_d,
                     float* __restrict__ als, float* __restrict__ ald,
                     int total, int H, int C)
{
    int w = (blockIdx.x * blockDim.x + threadIdx.x) >> 5;
    int lane = threadIdx.x & 31;
    if (w >= total) return;
    int n = w / H, hd = w - n * H;
    const float* hp = h + (size_t)n * H * C + (size_t)hd * C;
    const float* sp = a_s + (size_t)hd * C;
    const float* dp = a_d + (size_t)hd * C;
    float s = 0.f, d = 0.f;
    for (int c = lane; c < C; c += 32) {
        float hv = hp[c];
        s = fmaf(hv, sp[c], s);
        d = fmaf(hv, dp[c], d);
    }
    #pragma unroll
    for (int o = 16; o > 0; o >>= 1) {
        s += __shfl_down_sync(0xffffffffu, s, o);
        d += __shfl_down_sync(0xffffffffu, d, o);
    }
    if (lane == 0) { als[w] = s; ald[w] = d; }
}

__device__ __forceinline__ void softmax36(const float* ss, const float* sd,
                                          float (*aT)[40], int i)
{
    float di = sd[i];
    float ev[36];
    float m = -3.4e38f;
    #pragma unroll
    for (int j = 0; j < 36; j++) {
        float e = ss[j] + di;
        e = (e > 0.f) ? e : 0.2f * e;
        ev[j] = e;
        m = fmaxf(m, e);
    }
    float sum = 0.f;
    #pragma unroll
    for (int j = 0; j < 36; j++) { float x = expf(ev[j] - m); ev[j] = x; sum += x; }
    float inv = 1.0f / (sum + 1e-16f);
    #pragma unroll
    for (int j = 0; j < 36; j++) aT[j][i] = ev[j] * inv;
}

// GAT aggregation C=256 concat + relu (+residual)
__global__ __launch_bounds__(256) void gat_agg256(
    const float* __restrict__ h, const float* __restrict__ als, const float* __restrict__ ald,
    const float* __restrict__ bias, const float* __restrict__ resid,
    float* __restrict__ out, int H)
{
    __shared__ float sh[36][256];
    __shared__ float aT[36][40];
    __shared__ float ss[36], sd[36];

    const int bh = blockIdx.x;
    const int b = bh / H, hd = bh - b * H;
    const int tid = threadIdx.x;
    const int stride = H * 256;
    const float* hbase = h + (size_t)(b * NOBJ) * stride + hd * 256;

    for (int idx = tid; idx < 36 * 256; idx += 256) {
        int i = idx >> 8, c = idx & 255;
        sh[i][c] = hbase[(size_t)i * stride + c];
    }
    if (tid < 36) {
        ss[tid] = als[(size_t)(b * NOBJ + tid) * H + hd];
        sd[tid] = ald[(size_t)(b * NOBJ + tid) * H + hd];
    }
    __syncthreads();
    if (tid < 36) softmax36(ss, sd, aT, tid);
    __syncthreads();

    const int c = tid;
    float acc[36];
    #pragma unroll
    for (int i = 0; i < 36; i++) acc[i] = 0.f;

    #pragma unroll 4
    for (int j = 0; j < 36; j++) {
        float hv = sh[j][c];
        #pragma unroll
        for (int it = 0; it < 9; it++) {
            float4 a = *(const float4*)&aT[j][it * 4];
            acc[it*4+0] = fmaf(a.x, hv, acc[it*4+0]);
            acc[it*4+1] = fmaf(a.y, hv, acc[it*4+1]);
            acc[it*4+2] = fmaf(a.z, hv, acc[it*4+2]);
            acc[it*4+3] = fmaf(a.w, hv, acc[it*4+3]);
        }
    }

    float bv = bias[hd * 256 + c];
    #pragma unroll 4
    for (int i = 0; i < 36; i++) {
        size_t oi = (size_t)(b * NOBJ + i) * stride + hd * 256 + c;
        float o = fmaxf(acc[i] + bv, 0.f);
        if (resid) o += resid[oi];
        out[oi] = o;
    }
}

// GAT layer 3: C=512, H=5, mean over heads + b3
__global__ __launch_bounds__(256) void gat_mean_k(
    const float* __restrict__ h, const float* __restrict__ als, const float* __restrict__ ald,
    const float* __restrict__ bias, float* __restrict__ out)
{
    __shared__ float sh[36][256];
    __shared__ float aT[36][40];
    __shared__ float ss[36], sd[36];

    const int b = blockIdx.x;
    const int coff = blockIdx.y * 256;
    const int tid = threadIdx.x;

    float acc[36];
    #pragma unroll
    for (int i = 0; i < 36; i++) acc[i] = 0.f;

    for (int hd = 0; hd < 5; hd++) {
        __syncthreads();
        for (int idx = tid; idx < 36 * 256; idx += 256) {
            int i = idx >> 8, c = idx & 255;
            sh[i][c] = h[(size_t)(b * NOBJ + i) * 2560 + hd * 512 + coff + c];
        }
        if (tid < 36) {
            ss[tid] = als[(size_t)(b * NOBJ + tid) * 5 + hd];
            sd[tid] = ald[(size_t)(b * NOBJ + tid) * 5 + hd];
        }
        __syncthreads();
        if (tid < 36) softmax36(ss, sd, aT, tid);
        __syncthreads();

        const int c = tid;
        #pragma unroll 4
        for (int j = 0; j < 36; j++) {
            float hv = sh[j][c];
            #pragma unroll
            for (int it = 0; it < 9; it++) {
                float4 a = *(const float4*)&aT[j][it * 4];
                acc[it*4+0] = fmaf(a.x, hv, acc[it*4+0]);
                acc[it*4+1] = fmaf(a.y, hv, acc[it*4+1]);
                acc[it*4+2] = fmaf(a.z, hv, acc[it*4+2]);
                acc[it*4+3] = fmaf(a.w, hv, acc[it*4+3]);
            }
        }
    }

    float bv = bias[coff + tid];
    #pragma unroll 4
    for (int i = 0; i < 36; i++)
        out[(size_t)(b * NOBJ + i) * 512 + coff + tid] = acc[i] * 0.2f + bv;
}

// ==================== launch ====================
extern "C" void kernel_launch(void* const* d_in, const int* in_sizes, int n_in,
                              void* d_out, int out_size)
{
    const float* qe  = (const float*)d_in[0];
    const float* obj = (const float*)d_in[1];
    const float* Wq  = (const float*)d_in[3];
    const float* bq  = (const float*)d_in[4];
    const float* Wv  = (const float*)d_in[5];
    const float* bv  = (const float*)d_in[6];
    const float* W1  = (const float*)d_in[7];
    const float* a1s = (const float*)d_in[8];
    const float* a1d = (const float*)d_in[9];
    const float* b1  = (const float*)d_in[10];
    const float* W2  = (const float*)d_in[11];
    const float* a2s = (const float*)d_in[12];
    const float* a2d = (const float*)d_in[13];
    const float* b2  = (const float*)d_in[14];
    const float* W3  = (const float*)d_in[15];
    const float* a3s = (const float*)d_in[16];
    const float* a3d = (const float*)d_in[17];
    const float* b3  = (const float*)d_in[18];
    float* out = (float*)d_out;

    int8_t *qe1,*qe0,*ob1,*ob0,*Wq1,*Wq0,*Wv1,*Wv0,*W11,*W10,*W21,*W20,*W31,*W30;
    int8_t *x1,*x0,*g11,*g10,*g21,*g20;
    float *sQe,*sOb,*sWq,*sWv,*sW1,*sW2,*sW3,*sX,*sG1,*sG2;
    float *WTf,*q,*qpart,*xf,*h,*g1,*g2,*als,*ald;
    cudaGetSymbolAddress((void**)&qe1, g_qe1); cudaGetSymbolAddress((void**)&qe0, g_qe0);
    cudaGetSymbolAddress((void**)&ob1, g_ob1); cudaGetSymbolAddress((void**)&ob0, g_ob0);
    cudaGetSymbolAddress((void**)&Wq1, g_Wq1); cudaGetSymbolAddress((void**)&Wq0, g_Wq0);
    cudaGetSymbolAddress((void**)&Wv1, g_Wv1); cudaGetSymbolAddress((void**)&Wv0, g_Wv0);
    cudaGetSymbolAddress((void**)&W11, g_W11); cudaGetSymbolAddress((void**)&W10, g_W10);
    cudaGetSymbolAddress((void**)&W21, g_W21); cudaGetSymbolAddress((void**)&W20, g_W20);
    cudaGetSymbolAddress((void**)&W31, g_W31); cudaGetSymbolAddress((void**)&W30, g_W30);
    cudaGetSymbolAddress((void**)&x1,  g_x1);  cudaGetSymbolAddress((void**)&x0,  g_x0);
    cudaGetSymbolAddress((void**)&g11, g_g11); cudaGetSymbolAddress((void**)&g10, g_g10);
    cudaGetSymbolAddress((void**)&g21, g_g21); cudaGetSymbolAddress((void**)&g20, g_g20);
    cudaGetSymbolAddress((void**)&sQe, g_sQe); cudaGetSymbolAddress((void**)&sOb, g_sOb);
    cudaGetSymbolAddress((void**)&sWq, g_sWq); cudaGetSymbolAddress((void**)&sWv, g_sWv);
    cudaGetSymbolAddress((void**)&sW1, g_sW1); cudaGetSymbolAddress((void**)&sW2, g_sW2);
    cudaGetSymbolAddress((void**)&sW3, g_sW3); cudaGetSymbolAddress((void**)&sX,  g_sX);
    cudaGetSymbolAddress((void**)&sG1, g_sG1); cudaGetSymbolAddress((void**)&sG2, g_sG2);
    cudaGetSymbolAddress((void**)&WTf, g_WTf);
    cudaGetSymbolAddress((void**)&q,   g_q);   cudaGetSymbolAddress((void**)&qpart, g_qpart);
    cudaGetSymbolAddress((void**)&xf,  g_xf);  cudaGetSymbolAddress((void**)&h,   g_h);
    cudaGetSymbolAddress((void**)&g1,  g_g1);  cudaGetSymbolAddress((void**)&g2,  g_g2);
    cudaGetSymbolAddress((void**)&als, g_als); cudaGetSymbolAddress((void**)&ald, g_ald);

    cudaFuncSetAttribute(gemm_i8, cudaFuncAttributeMaxDynamicSharedMemorySize, GI_SMEM);

    // ---- input slicing ----
    slice_k<<<128, 256>>>(qe, QD, QDP, qe1, qe0, sQe);
    slice_k<<<NNODE, 256>>>(obj, 2048, 2048, ob1, ob0, sOb);

    // ---- weights: transpose to [N,Kp] then slice (sequential reuse of WTf) ----
    tr_k<<<dim3(2048/32, QDP/32), 256>>>(Wq, WTf, QD, 2048, QDP);
    slice_k<<<2048, 256>>>(WTf, QDP, QDP, Wq1, Wq0, sWq);
    tr_k<<<dim3(2048/32, 2048/32), 256>>>(Wv, WTf, 2048, 2048, 2048);
    slice_k<<<2048, 256>>>(WTf, 2048, 2048, Wv1, Wv0, sWv);
    tr_k<<<dim3(1024/32, 2048/32), 256>>>(W1, WTf, 2048, 1024, 2048);
    slice_k<<<1024, 256>>>(WTf, 2048, 2048, W11, W10, sW1);
    tr_k<<<dim3(1024/32, 1024/32), 256>>>(W2, WTf, 1024, 1024, 1024);
    slice_k<<<1024, 256>>>(WTf, 1024, 1024, W21, W20, sW2);
    tr_k<<<dim3(2560/32, 1024/32), 256>>>(W3, WTf, 1024, 2560, 1024);
    slice_k<<<2560, 256>>>(WTf, 1024, 1024, W31, W30, sW3);

    // ---- q = qe @ Wq (split-K 4) + bq ----
    gemm_i8<<<dim3(16, 1, 4), 256, GI_SMEM>>>(qe1, qe0, sQe, Wq1, Wq0, sWq,
                                              2048, QDP, 19, 5, nullptr, nullptr,
                                              qpart, 0, (size_t)128 * 2048);
    combq_k<<<(128 * 2048 + 255) / 256, 256>>>(qpart, bq, q);

    // ---- x = (obj @ Wv + bv) * q ----
    gemm_i8<<<dim3(16, 36, 1), 256, GI_SMEM>>>(ob1, ob0, sOb, Wv1, Wv0, sWv,
                                               2048, 2048, 16, 16, bv, q, xf, 2, 0);
    slice_k<<<NNODE, 256>>>(xf, 2048, 2048, x1, x0, sX);

    // ---- layer 1 ----
    gemm_i8<<<dim3(8, 36, 1), 256, GI_SMEM>>>(x1, x0, sX, W11, W10, sW1,
                                              1024, 2048, 16, 16, nullptr, nullptr, h, 0, 0);
    al_k<<<(NNODE * 4 * 32 + 255) / 256, 256>>>(h, a1s, a1d, als, ald, NNODE * 4, 4, 256);
    gat_agg256<<<BATCH * 4, 256>>>(h, als, ald, b1, nullptr, g1, 4);
    slice_k<<<NNODE, 256>>>(g1, 1024, 1024, g11, g10, sG1);

    // ---- layer 2 (+residual) ----
    gemm_i8<<<dim3(8, 36, 1), 256, GI_SMEM>>>(g11, g10, sG1, W21, W20, sW2,
                                              1024, 1024, 8, 8, nullptr, nullptr, h, 0, 0);
    al_k<<<(NNODE * 4 * 32 + 255) / 256, 256>>>(h, a2s, a2d, als, ald, NNODE * 4, 4, 256);
    gat_agg256<<<BATCH * 4, 256>>>(h, als, ald, b2, g1, g2, 4);
    slice_k<<<NNODE, 256>>>(g2, 1024, 1024, g21, g20, sG2);

    // ---- layer 3 (mean over 5 heads) ----
    gemm_i8<<<dim3(20, 36, 1), 256, GI_SMEM>>>(g21, g20, sG2, W31, W30, sW3,
                                               2560, 1024, 8, 8, nullptr, nullptr, h, 0, 0);
    al_k<<<(NNODE * 5 * 32 + 255) / 256, 256>>>(h, a3s, a3d, als, ald, NNODE * 5, 5, 512);
    gat_mean_k<<<dim3(BATCH, 2), 256>>>(h, als, ald, b3, out);

    (void)in_sizes; (void)n_in; (void)out_size;
}

// round 6
// speedup vs baseline: 3.2573x; 3.2573x over previous
#include <cuda_runtime.h>
#include <cuda_fp16.h>
#include <math.h>
#include <stdint.h>

// Problem constants
#define BATCH 128
#define NOBJ  36
#define NNODE (BATCH*NOBJ)   // 4608
#define QD    2400
#define QDP   2432

typedef __half fp16;

#define SWZ128(o) ((o) ^ (((o) >> 3) & 0x70))

__device__ __forceinline__ uint32_t smem_u32(const void* p) {
    uint32_t a;
    asm("{ .reg .u64 t; cvta.to.shared.u64 t, %1; cvt.u32.u64 %0, t; }" : "=r"(a) : "l"(p));
    return a;
}
__device__ __forceinline__ void cpa16(uint32_t s, const void* g) {
    asm volatile("cp.async.cg.shared.global [%0], [%1], 16;" :: "r"(s), "l"(g));
}
#define CP_COMMIT() asm volatile("cp.async.commit_group;" ::: "memory")
#define CP_WAIT1()  asm volatile("cp.async.wait_group 1;" ::: "memory")
#define CP_WAIT0()  asm volatile("cp.async.wait_group 0;" ::: "memory")

__device__ __forceinline__ void ldmx4(uint32_t& r0, uint32_t& r1, uint32_t& r2, uint32_t& r3, uint32_t addr) {
    asm volatile("ldmatrix.sync.aligned.m8n8.x4.shared.b16 {%0,%1,%2,%3}, [%4];"
                 : "=r"(r0), "=r"(r1), "=r"(r2), "=r"(r3) : "r"(addr));
}
__device__ __forceinline__ void mma16816(float* c, const uint32_t* a, uint32_t b0, uint32_t b1) {
    asm volatile(
        "mma.sync.aligned.m16n8k16.row.col.f32.f16.f16.f32 "
        "{%0,%1,%2,%3}, {%4,%5,%6,%7}, {%8,%9}, {%0,%1,%2,%3};"
        : "+f"(c[0]), "+f"(c[1]), "+f"(c[2]), "+f"(c[3])
        : "r"(a[0]), "r"(a[1]), "r"(a[2]), "r"(a[3]), "r"(b0), "r"(b1));
}

// ==================== scratch (no allocations allowed) ====================
__device__ __align__(128) fp16 g_qe16[128 * QDP];
__device__ __align__(128) fp16 g_ob16[NNODE * 2048];
__device__ __align__(128) fp16 g_WqTh[2048 * QDP];
__device__ __align__(128) fp16 g_WqTl[2048 * QDP];
__device__ __align__(128) fp16 g_WvTh[2048 * 2048];
__device__ __align__(128) fp16 g_WvTl[2048 * 2048];
__device__ __align__(128) fp16 g_W1Th[1024 * 2048];
__device__ __align__(128) fp16 g_W1Tl[1024 * 2048];
__device__ __align__(128) fp16 g_W2Th[1024 * 1024];
__device__ __align__(128) fp16 g_W2Tl[1024 * 1024];
__device__ __align__(128) fp16 g_W3Th[2560 * 1024];
__device__ __align__(128) fp16 g_W3Tl[2560 * 1024];
__device__ __align__(128) fp16 g_x16 [NNODE * 2048];
__device__ __align__(128) fp16 g_g116[NNODE * 1024];
__device__ __align__(128) fp16 g_g216[NNODE * 1024];

__device__ float g_q    [128 * 2048];
__device__ float g_qpart[4 * 128 * 2048];
__device__ float g_h    [NNODE * 2560];
__device__ float g_g1   [NNODE * 1024];
__device__ float g_g2   [NNODE * 1024];
__device__ float g_als  [NNODE * 5];
__device__ float g_ald  [NNODE * 5];

// ==================== conversion kernels ====================
// fp32 [R,C] -> fp16 [R,Cp] (zero pad)
__global__ void conv16_k(const float* __restrict__ in, fp16* __restrict__ o16, int R, int C, int Cp)
{
    int idx = blockIdx.x * blockDim.x + threadIdx.x;
    int cq = Cp >> 2;
    if (idx >= R * cq) return;
    int r = idx / cq;
    int c4 = (idx - r * cq) * 4;
    float4 v = make_float4(0.f, 0.f, 0.f, 0.f);
    if (c4 < C) v = *(const float4*)(in + (size_t)r * C + c4);
    __half2 p0 = __floats2half2_rn(v.x, v.y);
    __half2 p1 = __floats2half2_rn(v.z, v.w);
    *(__half2*)(o16 + (size_t)r * Cp + c4)     = p0;
    *(__half2*)(o16 + (size_t)r * Cp + c4 + 2) = p1;
}

// transpose + fp16 2-split: W fp32 [K,N] -> Th/Tl fp16 [N,Kp]
__global__ __launch_bounds__(256) void tsplit_k(const float* __restrict__ W,
                                                fp16* __restrict__ Th, fp16* __restrict__ Tl,
                                                int K, int N, int Kp)
{
    __shared__ float t[32][33];
    int n0 = blockIdx.x * 32, k0 = blockIdx.y * 32;
    int tx = threadIdx.x & 31, ty = threadIdx.x >> 5;
    #pragma unroll
    for (int i = 0; i < 4; i++) {
        int k = k0 + ty + i * 8;
        t[ty + i * 8][tx] = (k < K) ? W[(size_t)k * N + n0 + tx] : 0.f;
    }
    __syncthreads();
    #pragma unroll
    for (int i = 0; i < 4; i++) {
        int n = n0 + ty + i * 8;
        int k = k0 + tx;
        float v = t[tx][ty + i * 8];
        fp16 h = __float2half_rn(v);
        fp16 l = __float2half_rn(v - __half2float(h));
        Th[(size_t)n * Kp + k] = h;
        Tl[(size_t)n * Kp + k] = l;
    }
}

__global__ void combq_k(const float* __restrict__ parts, const float* __restrict__ bq, float* __restrict__ q)
{
    int idx = blockIdx.x * blockDim.x + threadIdx.x;
    if (idx >= 128 * 2048) return;
    const size_t S = (size_t)128 * 2048;
    int c = idx & 2047;
    q[idx] = bq[c] + parts[idx] + parts[idx + S] + parts[idx + 2*S] + parts[idx + 3*S];
}

// ==================== fp16 2-term GEMM ====================
// C[M,N] = A[M,Kp] @ (Bh+Bl)[N,Kp]^T ; CTA tile 128x256, KC=64, 512 threads
// 16 warps in 4x4 grid, warp tile 32x64
// mode 0: Cf[splitStride*z + row*N+col] = acc
// mode 2: Cf not used; C16[row*N+col] = fp16((acc + bias[col]) * qmul[(row/36)*N+col]),
//         also writes fp32 copy to Cf
#define KC 64
#define BUFSZ 81920u          // A 16K + Bh 32K + Bl 32K
#define GEMM_SMEM (2*BUFSZ + 1024)

__global__ __launch_bounds__(512, 1) void gemm2(
    const fp16* __restrict__ A,
    const fp16* __restrict__ Bh, const fp16* __restrict__ Bl,
    int N, int Kp, int kcTotal, int kcPerSplit,
    const float* __restrict__ bias, const float* __restrict__ qmul,
    float* __restrict__ Cf, fp16* __restrict__ C16,
    int mode, size_t splitStride)
{
    extern __shared__ char dsm[];
    uint32_t sb = smem_u32(dsm);
    sb = (sb + 1023u) & ~1023u;

    const int tid = threadIdx.x;
    const int wid = tid >> 5;
    const int L   = tid & 31;
    const int m0 = blockIdx.y * 128;
    const int n0 = blockIdx.x * 256;
    const int kc0 = blockIdx.z * kcPerSplit;
    int kc1 = kc0 + kcPerSplit; if (kc1 > kcTotal) kc1 = kcTotal;
    const int ncl = kc1 - kc0;

    const int wm = (wid & 3) * 32;     // 4 warp-rows
    const int wn = (wid >> 2) * 64;    // 4 warp-cols

    float acc[2][8][4];
    #pragma unroll
    for (int i = 0; i < 2; i++)
        #pragma unroll
        for (int j = 0; j < 8; j++)
            #pragma unroll
            for (int k = 0; k < 4; k++) acc[i][j][k] = 0.f;

    // ldmatrix per-lane addressing (SW128 over 128B rows)
    const int rA = ((L >> 3) & 1) * 8 + (L & 7);
    const int cA = (L >> 4) * 16;
    const int rB = (L >> 4) * 8 + (L & 7);
    const int cB = ((L >> 3) & 1) * 16;

    uint32_t offA[2], mskA[2];
    #pragma unroll
    for (int mf = 0; mf < 2; mf++) {
        int row = wm + mf * 16 + rA;
        offA[mf] = (uint32_t)(row * 128);
        mskA[mf] = (uint32_t)((row & 7) * 16);
    }
    uint32_t offB[4], mskB[4];
    #pragma unroll
    for (int nf2 = 0; nf2 < 4; nf2++) {
        int row = wn + nf2 * 16 + rB;
        offB[nf2] = (uint32_t)(row * 128);
        mskB[nf2] = (uint32_t)((row & 7) * 16);
    }

    // layout per buffer: A @0 (16KB), Bh @16K (32KB), Bl @48K (32KB)
    auto load_chunk = [&](int c, int s) {
        const int k0 = c * KC;
        uint32_t base = sb + (uint32_t)s * BUFSZ;
        #pragma unroll
        for (int i = 0; i < 2; i++) {            // A: 1024 units
            int u = tid + i * 512;
            int r = u >> 3, uc = u & 7;
            uint32_t so = SWZ128((uint32_t)(r * 128 + uc * 16));
            cpa16(base + so, A + (size_t)(m0 + r) * Kp + k0 + uc * 8);
        }
        #pragma unroll
        for (int i = 0; i < 4; i++) {            // B: 2048 units each
            int u = tid + i * 512;
            int r = u >> 3, uc = u & 7;
            uint32_t so = SWZ128((uint32_t)(r * 128 + uc * 16));
            size_t go = (size_t)(n0 + r) * Kp + k0 + uc * 8;
            cpa16(base + 16384u + so, Bh + go);
            cpa16(base + 49152u + so, Bl + go);
        }
    };

    load_chunk(kc0, 0); CP_COMMIT();

    for (int cc = 0; cc < ncl; cc++) {
        if (cc + 1 < ncl) {
            load_chunk(kc0 + cc + 1, (cc + 1) & 1);
            CP_COMMIT();
            CP_WAIT1();
        } else {
            CP_WAIT0();
        }
        __syncthreads();

        uint32_t base = sb + (uint32_t)(cc & 1) * BUFSZ;
        #pragma unroll
        for (int ks = 0; ks < 4; ks++) {
            const uint32_t kb = (uint32_t)(ks * 32);
            uint32_t af[2][4];
            #pragma unroll
            for (int mf = 0; mf < 2; mf++) {
                uint32_t rel = offA[mf] + ((kb + cA) ^ mskA[mf]);
                ldmx4(af[mf][0], af[mf][1], af[mf][2], af[mf][3], base + rel);
            }
            #pragma unroll
            for (int nf2 = 0; nf2 < 4; nf2++) {
                uint32_t rel = offB[nf2] + ((kb + cB) ^ mskB[nf2]);
                uint32_t bh[4], bl[4];
                ldmx4(bh[0], bh[1], bh[2], bh[3], base + 16384u + rel);
                ldmx4(bl[0], bl[1], bl[2], bl[3], base + 49152u + rel);
                #pragma unroll
                for (int mf = 0; mf < 2; mf++) {
                    mma16816(acc[mf][nf2*2],   af[mf], bh[0], bh[1]);
                    mma16816(acc[mf][nf2*2],   af[mf], bl[0], bl[1]);
                    mma16816(acc[mf][nf2*2+1], af[mf], bh[2], bh[3]);
                    mma16816(acc[mf][nf2*2+1], af[mf], bl[2], bl[3]);
                }
            }
        }
        __syncthreads();
    }

    // epilogue
    const int rEp = (L >> 2);
    const int cEp = (L & 3) * 2;
    #pragma unroll
    for (int mf = 0; mf < 2; mf++) {
        #pragma unroll
        for (int half = 0; half < 2; half++) {
            int row = m0 + wm + mf * 16 + rEp + half * 8;
            if (mode == 0) {
                float* dst = Cf + splitStride * blockIdx.z + (size_t)row * N;
                #pragma unroll
                for (int nf = 0; nf < 8; nf++) {
                    int col = n0 + wn + nf * 8 + cEp;
                    float2 v;
                    v.x = acc[mf][nf][half*2 + 0];
                    v.y = acc[mf][nf][half*2 + 1];
                    *(float2*)(dst + col) = v;
                }
            } else {  // mode 2: hadamard, write fp16
                const float* qrow = qmul + (size_t)(row / NOBJ) * N;
                fp16* d16 = C16 + (size_t)row * N;
                #pragma unroll
                for (int nf = 0; nf < 8; nf++) {
                    int col = n0 + wn + nf * 8 + cEp;
                    float o0 = (acc[mf][nf][half*2+0] + bias[col])   * qrow[col];
                    float o1 = (acc[mf][nf][half*2+1] + bias[col+1]) * qrow[col+1];
                    *(__half2*)(d16 + col) = __floats2half2_rn(o0, o1);
                }
            }
        }
    }
}

// ==================== attention logits ====================
__global__ void al_k(const float* __restrict__ h,
                     const float* __restrict__ a_s, const float* __restrict__ a_d,
                     float* __restrict__ als, float* __restrict__ ald,
                     int total, int H, int C)
{
    int w = (blockIdx.x * blockDim.x + threadIdx.x) >> 5;
    int lane = threadIdx.x & 31;
    if (w >= total) return;
    int n = w / H, hd = w - n * H;
    const float* hp = h + (size_t)n * H * C + (size_t)hd * C;
    const float* sp = a_s + (size_t)hd * C;
    const float* dp = a_d + (size_t)hd * C;
    float s = 0.f, d = 0.f;
    for (int c = lane; c < C; c += 32) {
        float hv = hp[c];
        s = fmaf(hv, sp[c], s);
        d = fmaf(hv, dp[c], d);
    }
    #pragma unroll
    for (int o = 16; o > 0; o >>= 1) {
        s += __shfl_down_sync(0xffffffffu, s, o);
        d += __shfl_down_sync(0xffffffffu, d, o);
    }
    if (lane == 0) { als[w] = s; ald[w] = d; }
}

__device__ __forceinline__ void softmax36(const float* ss, const float* sd,
                                          float (*aT)[40], int i)
{
    float di = sd[i];
    float ev[36];
    float m = -3.4e38f;
    #pragma unroll
    for (int j = 0; j < 36; j++) {
        float e = ss[j] + di;
        e = (e > 0.f) ? e : 0.2f * e;
        ev[j] = e;
        m = fmaxf(m, e);
    }
    float sum = 0.f;
    #pragma unroll
    for (int j = 0; j < 36; j++) { float x = expf(ev[j] - m); ev[j] = x; sum += x; }
    float inv = 1.0f / (sum + 1e-16f);
    #pragma unroll
    for (int j = 0; j < 36; j++) aT[j][i] = ev[j] * inv;
}

// GAT aggregation C=256 concat + relu (+residual), write fp32 + fp16
__global__ __launch_bounds__(256) void gat_agg256(
    const float* __restrict__ h, const float* __restrict__ als, const float* __restrict__ ald,
    const float* __restrict__ bias, const float* __restrict__ resid,
    float* __restrict__ out, fp16* __restrict__ out16, int H)
{
    __shared__ float sh[36][256];
    __shared__ float aT[36][40];
    __shared__ float ss[36], sd[36];

    const int bh = blockIdx.x;
    const int b = bh / H, hd = bh - b * H;
    const int tid = threadIdx.x;
    const int stride = H * 256;
    const float* hbase = h + (size_t)(b * NOBJ) * stride + hd * 256;

    for (int idx = tid; idx < 36 * 256; idx += 256) {
        int i = idx >> 8, c = idx & 255;
        sh[i][c] = hbase[(size_t)i * stride + c];
    }
    if (tid < 36) {
        ss[tid] = als[(size_t)(b * NOBJ + tid) * H + hd];
        sd[tid] = ald[(size_t)(b * NOBJ + tid) * H + hd];
    }
    __syncthreads();
    if (tid < 36) softmax36(ss, sd, aT, tid);
    __syncthreads();

    const int c = tid;
    float acc[36];
    #pragma unroll
    for (int i = 0; i < 36; i++) acc[i] = 0.f;

    #pragma unroll 4
    for (int j = 0; j < 36; j++) {
        float hv = sh[j][c];
        #pragma unroll
        for (int it = 0; it < 9; it++) {
            float4 a = *(const float4*)&aT[j][it * 4];
            acc[it*4+0] = fmaf(a.x, hv, acc[it*4+0]);
            acc[it*4+1] = fmaf(a.y, hv, acc[it*4+1]);
            acc[it*4+2] = fmaf(a.z, hv, acc[it*4+2]);
            acc[it*4+3] = fmaf(a.w, hv, acc[it*4+3]);
        }
    }

    float bv = bias[hd * 256 + c];
    #pragma unroll 4
    for (int i = 0; i < 36; i++) {
        size_t oi = (size_t)(b * NOBJ + i) * stride + hd * 256 + c;
        float o = fmaxf(acc[i] + bv, 0.f);
        if (resid) o += resid[oi];
        out[oi] = o;
        out16[oi] = __float2half_rn(o);
    }
}

// GAT layer 3: C=512, H=5, mean over heads + b3
__global__ __launch_bounds__(256) void gat_mean_k(
    const float* __restrict__ h, const float* __restrict__ als, const float* __restrict__ ald,
    const float* __restrict__ bias, float* __restrict__ out)
{
    __shared__ float sh[36][256];
    __shared__ float aT[36][40];
    __shared__ float ss[36], sd[36];

    const int b = blockIdx.x;
    const int coff = blockIdx.y * 256;
    const int tid = threadIdx.x;

    float acc[36];
    #pragma unroll
    for (int i = 0; i < 36; i++) acc[i] = 0.f;

    for (int hd = 0; hd < 5; hd++) {
        __syncthreads();
        for (int idx = tid; idx < 36 * 256; idx += 256) {
            int i = idx >> 8, c = idx & 255;
            sh[i][c] = h[(size_t)(b * NOBJ + i) * 2560 + hd * 512 + coff + c];
        }
        if (tid < 36) {
            ss[tid] = als[(size_t)(b * NOBJ + tid) * 5 + hd];
            sd[tid] = ald[(size_t)(b * NOBJ + tid) * 5 + hd];
        }
        __syncthreads();
        if (tid < 36) softmax36(ss, sd, aT, tid);
        __syncthreads();

        const int c = tid;
        #pragma unroll 4
        for (int j = 0; j < 36; j++) {
            float hv = sh[j][c];
            #pragma unroll
            for (int it = 0; it < 9; it++) {
                float4 a = *(const float4*)&aT[j][it * 4];
                acc[it*4+0] = fmaf(a.x, hv, acc[it*4+0]);
                acc[it*4+1] = fmaf(a.y, hv, acc[it*4+1]);
                acc[it*4+2] = fmaf(a.z, hv, acc[it*4+2]);
                acc[it*4+3] = fmaf(a.w, hv, acc[it*4+3]);
            }
        }
    }

    float bv = bias[coff + tid];
    #pragma unroll 4
    for (int i = 0; i < 36; i++)
        out[(size_t)(b * NOBJ + i) * 512 + coff + tid] = acc[i] * 0.2f + bv;
}

// ==================== launch ====================
extern "C" void kernel_launch(void* const* d_in, const int* in_sizes, int n_in,
                              void* d_out, int out_size)
{
    const float* qe  = (const float*)d_in[0];
    const float* obj = (const float*)d_in[1];
    const float* Wq  = (const float*)d_in[3];
    const float* bq  = (const float*)d_in[4];
    const float* Wv  = (const float*)d_in[5];
    const float* bv  = (const float*)d_in[6];
    const float* W1  = (const float*)d_in[7];
    const float* a1s = (const float*)d_in[8];
    const float* a1d = (const float*)d_in[9];
    const float* b1  = (const float*)d_in[10];
    const float* W2  = (const float*)d_in[11];
    const float* a2s = (const float*)d_in[12];
    const float* a2d = (const float*)d_in[13];
    const float* b2  = (const float*)d_in[14];
    const float* W3  = (const float*)d_in[15];
    const float* a3s = (const float*)d_in[16];
    const float* a3d = (const float*)d_in[17];
    const float* b3  = (const float*)d_in[18];
    float* out = (float*)d_out;

    fp16 *qe16,*ob16,*WqTh,*WqTl,*WvTh,*WvTl,*W1Th,*W1Tl,*W2Th,*W2Tl,*W3Th,*W3Tl;
    fp16 *x16,*g116,*g216;
    float *q,*qpart,*h,*g1,*g2,*als,*ald;
    cudaGetSymbolAddress((void**)&qe16, g_qe16); cudaGetSymbolAddress((void**)&ob16, g_ob16);
    cudaGetSymbolAddress((void**)&WqTh, g_WqTh); cudaGetSymbolAddress((void**)&WqTl, g_WqTl);
    cudaGetSymbolAddress((void**)&WvTh, g_WvTh); cudaGetSymbolAddress((void**)&WvTl, g_WvTl);
    cudaGetSymbolAddress((void**)&W1Th, g_W1Th); cudaGetSymbolAddress((void**)&W1Tl, g_W1Tl);
    cudaGetSymbolAddress((void**)&W2Th, g_W2Th); cudaGetSymbolAddress((void**)&W2Tl, g_W2Tl);
    cudaGetSymbolAddress((void**)&W3Th, g_W3Th); cudaGetSymbolAddress((void**)&W3Tl, g_W3Tl);
    cudaGetSymbolAddress((void**)&x16,  g_x16);
    cudaGetSymbolAddress((void**)&g116, g_g116); cudaGetSymbolAddress((void**)&g216, g_g216);
    cudaGetSymbolAddress((void**)&q,    g_q);    cudaGetSymbolAddress((void**)&qpart,g_qpart);
    cudaGetSymbolAddress((void**)&h,    g_h);
    cudaGetSymbolAddress((void**)&g1,   g_g1);   cudaGetSymbolAddress((void**)&g2,   g_g2);
    cudaGetSymbolAddress((void**)&als,  g_als);  cudaGetSymbolAddress((void**)&ald,  g_ald);

    cudaFuncSetAttribute(gemm2, cudaFuncAttributeMaxDynamicSharedMemorySize, GEMM_SMEM);

    // conversions / weight prep
    conv16_k<<<(128 * (QDP/4) + 255) / 256, 256>>>(qe, qe16, 128, QD, QDP);
    conv16_k<<<(NNODE * (2048/4) + 255) / 256, 256>>>(obj, ob16, NNODE, 2048, 2048);
    tsplit_k<<<dim3(2048/32, QDP/32), 256>>>(Wq, WqTh, WqTl, QD, 2048, QDP);
    tsplit_k<<<dim3(2048/32, 2048/32), 256>>>(Wv, WvTh, WvTl, 2048, 2048, 2048);
    tsplit_k<<<dim3(1024/32, 2048/32), 256>>>(W1, W1Th, W1Tl, 2048, 1024, 2048);
    tsplit_k<<<dim3(1024/32, 1024/32), 256>>>(W2, W2Th, W2Tl, 1024, 1024, 1024);
    tsplit_k<<<dim3(2560/32, 1024/32), 256>>>(W3, W3Th, W3Tl, 1024, 2560, 1024);

    // q = qe @ Wq (split-K 4) + bq
    gemm2<<<dim3(8, 1, 4), 512, GEMM_SMEM>>>(qe16, WqTh, WqTl, 2048, QDP, 38, 10,
                                             nullptr, nullptr, qpart, nullptr, 0,
                                             (size_t)128 * 2048);
    combq_k<<<(128 * 2048 + 255) / 256, 256>>>(qpart, bq, q);

    // x = (obj @ Wv + bv) * q  -> fp16
    gemm2<<<dim3(8, 36, 1), 512, GEMM_SMEM>>>(ob16, WvTh, WvTl, 2048, 2048, 32, 32,
                                              bv, q, nullptr, x16, 2, 0);

    // layer 1
    gemm2<<<dim3(4, 36, 1), 512, GEMM_SMEM>>>(x16, W1Th, W1Tl, 1024, 2048, 32, 32,
                                              nullptr, nullptr, h, nullptr, 0, 0);
    al_k<<<(NNODE * 4 * 32 + 255) / 256, 256>>>(h, a1s, a1d, als, ald, NNODE * 4, 4, 256);
    gat_agg256<<<BATCH * 4, 256>>>(h, als, ald, b1, nullptr, g1, g116, 4);

    // layer 2 (+residual)
    gemm2<<<dim3(4, 36, 1), 512, GEMM_SMEM>>>(g116, W2Th, W2Tl, 1024, 1024, 16, 16,
                                              nullptr, nullptr, h, nullptr, 0, 0);
    al_k<<<(NNODE * 4 * 32 + 255) / 256, 256>>>(h, a2s, a2d, als, ald, NNODE * 4, 4, 256);
    gat_agg256<<<BATCH * 4, 256>>>(h, als, ald, b2, g1, g2, g216, 4);

    // layer 3 (mean over 5 heads)
    gemm2<<<dim3(10, 36, 1), 512, GEMM_SMEM>>>(g216, W3Th, W3Tl, 2560, 1024, 16, 16,
                                               nullptr, nullptr, h, nullptr, 0, 0);
    al_k<<<(NNODE * 5 * 32 + 255) / 256, 256>>>(h, a3s, a3d, als, ald, NNODE * 5, 5, 512);
    gat_mean_k<<<dim3(BATCH, 2), 256>>>(h, als, ald, b3, out);

    (void)in_sizes; (void)n_in; (void)out_size;
}